// round 16
// baseline (speedup 1.0000x reference)
#include <cuda_runtime.h>
#include <cuda_bf16.h>
#include <cstdint>

#define NMAX    50048
#define EMAX    800000
#define ETOTMAX (NMAX + EMAX)
#define NBLKMAX 256

// ------------------------- scratch (device globals) -------------------------
__device__ __align__(16) float g_xl1[NMAX * 128];
__device__ __align__(16) float g_xr1[NMAX * 128];
__device__ __align__(16) float g_xl2[NMAX * 64];
__device__ __align__(16) float g_xr2[NMAX * 64];
// bf16 hi/lo GEMM inputs, PERMUTED k-order within each row (see permk)
__device__ __align__(16) __nv_bfloat16 g_xh [NMAX * 128];
__device__ __align__(16) __nv_bfloat16 g_xlo[NMAX * 128];
__device__ __align__(16) __nv_bfloat16 g_h1h[NMAX * 128];
__device__ __align__(16) __nv_bfloat16 g_h1l[NMAX * 128];
__device__ __align__(16) __nv_bfloat16 g_h2h[NMAX * 64];
__device__ __align__(16) __nv_bfloat16 g_h2l[NMAX * 64];
// weights, transposed to [col][k] with permuted k, bf16 hi/lo
__device__ __align__(16) __nv_bfloat16 g_w1h[2 * 128 * 128];
__device__ __align__(16) __nv_bfloat16 g_w1l[2 * 128 * 128];
__device__ __align__(16) __nv_bfloat16 g_w2h[2 * 64 * 128];
__device__ __align__(16) __nv_bfloat16 g_w2l[2 * 64 * 128];
__device__ __align__(16) __nv_bfloat16 g_w3h[128 * 64];
__device__ __align__(16) __nv_bfloat16 g_w3l[128 * 64];
// CSR   (g_deg is ZERO at module load; k_finalize re-zeros it each run)
__device__ __align__(16) int g_deg[NMAX];
__device__ __align__(16) int g_pre[NMAX];
__device__ __align__(16) int g_bsum[NBLKMAX];
__device__ __align__(16) int g_rowptr[NMAX + 1];
__device__ __align__(16) int g_cursor[NMAX];
__device__ __align__(16) int g_esrc[ETOTMAX];

// ------------------------- helpers -------------------------
__device__ __forceinline__ float elu1(float v) { return v > 0.f ? v : expm1f(v); }

__device__ __forceinline__ void split_bf(float v, __nv_bfloat16& h, __nv_bfloat16& l) {
    h = __float2bfloat16_rn(v);
    l = __float2bfloat16_rn(v - __bfloat162float(h));
}

// permuted element index within a row: per 32-elem chunk, word j (2 elems) goes to
// slot pos(j) = (j%4)*4 + j/4, so a fragment thread's 4 words are one uint4.
__device__ __forceinline__ int permk(int k) {
    int chunk = k >> 5;
    int j = (k & 31) >> 1;
    int lo = k & 1;
    int pos = (j & 3) * 4 + (j >> 2);
    return chunk * 32 + pos * 2 + lo;
}

__device__ __forceinline__ void mma_bf16(float* c, const uint32_t* a, const uint32_t* b) {
    asm volatile(
        "mma.sync.aligned.m16n8k16.row.col.f32.bf16.bf16.f32 "
        "{%0,%1,%2,%3}, {%4,%5,%6,%7}, {%8,%9}, {%0,%1,%2,%3};\n"
        : "+f"(c[0]), "+f"(c[1]), "+f"(c[2]), "+f"(c[3])
        : "r"(a[0]), "r"(a[1]), "r"(a[2]), "r"(a[3]), "r"(b[0]), "r"(b[1]));
}

__device__ __forceinline__ uint32_t s2u(const void* p) {
    return (uint32_t)__cvta_generic_to_shared(p);
}
#define CP16(dst, src) \
    asm volatile("cp.async.cg.shared.global [%0], [%1], 16;\n" :: "r"(dst), "l"(src))
#define CP_COMMIT() asm volatile("cp.async.commit_group;\n" ::: "memory")
#define CP_WAIT0()  asm volatile("cp.async.wait_group 0;\n" ::: "memory")
#define CP_WAIT1()  asm volatile("cp.async.wait_group 1;\n" ::: "memory")

// ------------- side stream + events for CSR fork/join (created at load) -------------
static cudaStream_t g_s2;
static cudaEvent_t  g_evFork, g_evCsr;
namespace {
struct _StreamInit {
    _StreamInit() {
        cudaStreamCreateWithFlags(&g_s2, cudaStreamNonBlocking);
        cudaEventCreateWithFlags(&g_evFork, cudaEventDisableTiming);
        cudaEventCreateWithFlags(&g_evCsr, cudaEventDisableTiming);
    }
};
_StreamInit _streamInit;
}

// --------- merged conversion kernel: blocks [0, GW) do weights, rest do x ---------
__global__ void k_cvt(const float* __restrict__ x, int n,
                      const float* __restrict__ Wl1, const float* __restrict__ Wr1,
                      const float* __restrict__ Wl2, const float* __restrict__ Wr2,
                      const float* __restrict__ Wlin, int GW) {
    if ((int)blockIdx.x < GW) {
        int i = blockIdx.x * blockDim.x + threadIdx.x;   // 57344 total
        if (i < 32768) {                                  // L1: m, col(128), k(128)
            int m = i >> 14, r = i & 16383, c = r >> 7, k = r & 127;
            const float* W = m ? Wr1 : Wl1;
            int o = (m << 14) + (c << 7) + permk(k);
            split_bf(W[k * 128 + c], g_w1h[o], g_w1l[o]);
        } else if (i < 49152) {                           // L2: m, col(64), k(128)
            int j = i - 32768;
            int m = j >> 13, r = j & 8191, c = r >> 7, k = r & 127;
            const float* W = m ? Wr2 : Wl2;
            int o = (m << 13) + (c << 7) + permk(k);
            split_bf(W[k * 64 + c], g_w2h[o], g_w2l[o]);
        } else if (i < 57344) {                           // lin: col(128), k(64)
            int j = i - 49152;
            int c = j >> 6, k = j & 63;
            int o = (c << 6) + permk(k);
            split_bf(Wlin[k * 128 + c], g_w3h[o], g_w3l[o]);
        }
    } else {
        int i = ((blockIdx.x - GW) * blockDim.x + threadIdx.x) * 4;
        if (i < n) {
            float4 v = *(const float4*)(x + i);
            __nv_bfloat16 h[4], l[4];
            split_bf(v.x, h[0], l[0]); split_bf(v.y, h[1], l[1]);
            split_bf(v.z, h[2], l[2]); split_bf(v.w, h[3], l[3]);
            int base = i & ~127;
            int p0 = base + permk(i & 127);
            int p1 = base + permk((i & 127) + 2);
            *(uint32_t*)(g_xh  + p0) = *(uint32_t*)&h[0];
            *(uint32_t*)(g_xh  + p1) = *(uint32_t*)&h[2];
            *(uint32_t*)(g_xlo + p0) = *(uint32_t*)&l[0];
            *(uint32_t*)(g_xlo + p1) = *(uint32_t*)&l[2];
        }
    }
}

// ------------------------- CSR build -------------------------
__global__ void k_hist(const int* __restrict__ ei, int E) {
    int i = blockIdx.x * blockDim.x + threadIdx.x;
    if (i < E) atomicAdd(&g_deg[ei[E + i]], 1);
}
// block-level scan of (deg+1); deg itself stays un-reset until k_finalize
__global__ void k_scanblk(int N) {
    __shared__ int sh[256];
    int i = blockIdx.x * 256 + threadIdx.x;
    int v = (i < N) ? (g_deg[i] + 1) : 0;      // +1 = self-loop
    sh[threadIdx.x] = v;
    __syncthreads();
    for (int off = 1; off < 256; off <<= 1) {
        int t = (threadIdx.x >= off) ? sh[threadIdx.x - off] : 0;
        __syncthreads();
        sh[threadIdx.x] += t;
        __syncthreads();
    }
    if (i < N) g_pre[i] = sh[threadIdx.x] - v;   // exclusive
    if (threadIdx.x == 255) g_bsum[blockIdx.x] = sh[255];
}
// merged top-scan + finalize: every block redundantly scans g_bsum in smem
__global__ void k_finalize(int N, int Etot, int NB) {
    __shared__ int sh[256];
    __shared__ int exc[256];
    int t = threadIdx.x;
    int v = (t < NB) ? g_bsum[t] : 0;
    sh[t] = v;
    __syncthreads();
    for (int off = 1; off < 256; off <<= 1) {
        int u = (t >= off) ? sh[t - off] : 0;
        __syncthreads();
        sh[t] += u;
        __syncthreads();
    }
    exc[t] = sh[t] - v;
    __syncthreads();
    int i = blockIdx.x * 256 + t;
    if (i < N) {
        int rp = g_pre[i] + exc[i >> 8];
        g_rowptr[i] = rp;
        g_cursor[i] = rp + 1;
        g_esrc[rp] = i;                   // self-loop occupies first slot
        g_deg[i] = 0;                     // reset for next graph replay
        if (i == 0) g_rowptr[N] = Etot;
    }
}
__global__ void k_scatter(const int* __restrict__ ei, int E) {
    int i = blockIdx.x * blockDim.x + threadIdx.x;
    if (i < E) {
        int d = ei[E + i];
        int slot = atomicAdd(&g_cursor[d], 1);
        g_esrc[slot] = ei[i];
    }
}

// ----- bf16x3-split tensor GEMM, permuted-k inputs, 3-stage cp.async pipeline (R14) -----
// C[M,BN] = A[M,K] @ W[K,BN] + bias.  BM=128, BK=32, 256 thr = 8 warps (2m x 4n).
// ONE __syncthreads per chunk: fill targets buf c+2, compute reads buf c.
// SRC: 0 = g_xh/g_xlo (K=128), 1 = g_h1h/g_h1l (K=128), 2 = g_h2h/g_h2l (K=64).
// WSEL: 1 = g_w1 (+y*16384), 2 = g_w2 (+y*8192), 3 = g_w3.
// DSTSEL: 0 = Carg (ldc=BN), 1 = y-sel (xl1,xr1) ldc=128, 2 = y-sel (xl2,xr2) ldc=64.
template <int K, int BN, int ACT, int SRC, int WSEL, int DSTSEL>
__global__ __launch_bounds__(256, 2) void k_gemm_bf(const float* __restrict__ b0,
                                                    const float* __restrict__ b1,
                                                    float* __restrict__ Carg, int M) {
    const int NF = BN / 32;
    const int KU4 = K / 8;                    // uint4 per global row
    const int NC = K / 32;                    // k-chunks

    const __nv_bfloat16* Agh = (SRC == 0) ? g_xh : (SRC == 1 ? g_h1h : g_h2h);
    const __nv_bfloat16* Agl = (SRC == 0) ? g_xlo : (SRC == 1 ? g_h1l : g_h2l);
    const __nv_bfloat16* Bgh = (WSEL == 1) ? g_w1h + blockIdx.y * 16384
                              : (WSEL == 2) ? g_w2h + blockIdx.y * 8192 : g_w3h;
    const __nv_bfloat16* Bgl = (WSEL == 1) ? g_w1l + blockIdx.y * 16384
                              : (WSEL == 2) ? g_w2l + blockIdx.y * 8192 : g_w3l;
    const float* bias = (blockIdx.y == 0) ? b0 : b1;
    float* C;
    int ldc;
    if (DSTSEL == 0)      { C = Carg; ldc = BN; }
    else if (DSTSEL == 1) { C = (blockIdx.y == 0) ? g_xl1 : g_xr1; ldc = 128; }
    else                  { C = (blockIdx.y == 0) ? g_xl2 : g_xr2; ldc = 64; }

    // 3-stage buffers; rows of exactly 64B -> conflict-free LDS.128 frags
    __shared__ __nv_bfloat16 Ah[3][128][32];
    __shared__ __nv_bfloat16 Al[3][128][32];
    __shared__ __nv_bfloat16 Bh[3][BN][32];
    __shared__ __nv_bfloat16 Bl[3][BN][32];

    int tid  = threadIdx.x;
    int lane = tid & 31;
    int ww   = tid >> 5;
    int bm   = blockIdx.x * 128;
    int wm0  = (ww & 1) * 64;
    int wn0  = (ww >> 1) * (BN / 4);
    int tg   = lane & 3;
    int gid  = lane >> 2;

    // per-thread fill coordinates (chunk-invariant)
    int fa_row = tid >> 1, fa_q = (tid & 1) * 2;
    int fa_arow = bm + fa_row; if (fa_arow >= M) fa_arow = M - 1;
    const uint4* fa_ph = (const uint4*)Agh + (size_t)fa_arow * KU4;
    const uint4* fa_pl = (const uint4*)Agl + (size_t)fa_arow * KU4;

    float acc[4][NF][4] = {};

    auto fill = [&](int buf, int c) {
        int ck4 = c * 4;
        CP16(s2u(&Ah[buf][fa_row][fa_q * 8]),       fa_ph + ck4 + fa_q);
        CP16(s2u(&Ah[buf][fa_row][(fa_q + 1) * 8]), fa_ph + ck4 + fa_q + 1);
        CP16(s2u(&Al[buf][fa_row][fa_q * 8]),       fa_pl + ck4 + fa_q);
        CP16(s2u(&Al[buf][fa_row][(fa_q + 1) * 8]), fa_pl + ck4 + fa_q + 1);
#pragma unroll
        for (int q = tid; q < BN * 4; q += 256) {
            int col = q >> 2, part = q & 3;
            CP16(s2u(&Bh[buf][col][part * 8]),
                 (const uint4*)Bgh + (size_t)col * KU4 + ck4 + part);
            CP16(s2u(&Bl[buf][col][part * 8]),
                 (const uint4*)Bgl + (size_t)col * KU4 + ck4 + part);
        }
    };

    fill(0, 0);
    CP_COMMIT();
    if (NC > 1) { fill(1, 1); CP_COMMIT(); }

#pragma unroll
    for (int c = 0; c < NC; c++) {
        int buf = c % 3;
        if (c + 1 < NC) CP_WAIT1(); else CP_WAIT0();
        __syncthreads();                       // buf c ready; compute(c-1) done everywhere
        if (c + 2 < NC) { fill((c + 2) % 3, c + 2); CP_COMMIT(); }

        // B fragments for whole k-chunk (both k16 steps): 2*NF LDS.128
        uint4 vbh[NF], vbl[NF];
#pragma unroll
        for (int in = 0; in < NF; in++) {
            int nc = wn0 + in * 8 + gid;
            vbh[in] = *(const uint4*)&Bh[buf][nc][tg * 8];
            vbl[in] = *(const uint4*)&Bl[buf][nc][tg * 8];
        }

#pragma unroll
        for (int im = 0; im < 4; im++) {
            int mr = wm0 + im * 16 + gid;
            uint4 vh = *(const uint4*)&Ah[buf][mr][tg * 8];
            uint4 uh = *(const uint4*)&Ah[buf][mr + 8][tg * 8];
            uint4 vl = *(const uint4*)&Al[buf][mr][tg * 8];
            uint4 ul = *(const uint4*)&Al[buf][mr + 8][tg * 8];
            uint32_t ah0[4] = {vh.x, uh.x, vh.y, uh.y};   // s = 0
            uint32_t ah1[4] = {vh.z, uh.z, vh.w, uh.w};   // s = 1
            uint32_t al0[4] = {vl.x, ul.x, vl.y, ul.y};
            uint32_t al1[4] = {vl.z, ul.z, vl.w, ul.w};
#pragma unroll
            for (int in = 0; in < NF; in++) {
                uint32_t bh0[2] = {vbh[in].x, vbh[in].y};
                uint32_t bh1[2] = {vbh[in].z, vbh[in].w};
                uint32_t bl0[2] = {vbl[in].x, vbl[in].y};
                uint32_t bl1[2] = {vbl[in].z, vbl[in].w};
                mma_bf16(acc[im][in], ah0, bh0);
                mma_bf16(acc[im][in], ah0, bl0);
                mma_bf16(acc[im][in], al0, bh0);
                mma_bf16(acc[im][in], ah1, bh1);
                mma_bf16(acc[im][in], ah1, bl1);
                mma_bf16(acc[im][in], al1, bh1);
            }
        }
    }

#pragma unroll
    for (int im = 0; im < 4; im++) {
        int r0 = bm + wm0 + im * 16 + gid;
#pragma unroll
        for (int in = 0; in < NF; in++) {
            int cc = wn0 + in * 8 + 2 * tg;
            float bx = bias[cc], by = bias[cc + 1];
            if (r0 < M) {
                float2 v = make_float2(acc[im][in][0] + bx, acc[im][in][1] + by);
                if (ACT) { v.x = elu1(v.x); v.y = elu1(v.y); }
                *(float2*)(C + (size_t)r0 * ldc + cc) = v;
            }
            if (r0 + 8 < M) {
                float2 v = make_float2(acc[im][in][2] + bx, acc[im][in][3] + by);
                if (ACT) { v.x = elu1(v.x); v.y = elu1(v.y); }
                *(float2*)(C + (size_t)(r0 + 8) * ldc + cc) = v;
            }
        }
    }
}

// --------- layer 1 edge phase, CSR, warp per node, 4-deep gather prefetch ---------
__global__ void k_edge1_csr(const float* __restrict__ att,
                            const float* __restrict__ bias, int N) {
    int gt = blockIdx.x * blockDim.x + threadIdx.x;
    int lane = gt & 31, w = gt >> 5;
    if (w >= N) return;

    float4 attr = *(const float4*)(att + lane * 4);
    float4 b = *(const float4*)(g_xr1 + (size_t)w * 128 + lane * 4);

    int beg = g_rowptr[w];
    int n = g_rowptr[w + 1] - beg;
    float4 acc = make_float4(0.f, 0.f, 0.f, 0.f);
    float den = 0.f;

    float4 buf[4];
#pragma unroll
    for (int j = 0; j < 4; j++)
        if (j < n)
            buf[j] = *(const float4*)(g_xl1 + (size_t)g_esrc[beg + j] * 128 + lane * 4);

    for (int p0 = 0; p0 < n; p0 += 4) {
#pragma unroll
        for (int j = 0; j < 4; j++) {
            int p = p0 + j;
            if (p < n) {
                float4 ac = buf[j];
                if (p + 4 < n)
                    buf[j] = *(const float4*)(g_xl1 + (size_t)g_esrc[beg + p + 4] * 128 + lane * 4);
                float z0 = ac.x + b.x; z0 = z0 > 0.f ? z0 : 0.2f * z0;
                float z1 = ac.y + b.y; z1 = z1 > 0.f ? z1 : 0.2f * z1;
                float z2 = ac.z + b.z; z2 = z2 > 0.f ? z2 : 0.2f * z2;
                float z3 = ac.w + b.w; z3 = z3 > 0.f ? z3 : 0.2f * z3;
                float part = attr.x * z0 + attr.y * z1 + attr.z * z2 + attr.w * z3;
                part += __shfl_xor_sync(0xffffffffu, part, 1);
                part += __shfl_xor_sync(0xffffffffu, part, 2);
                float ex = __expf(part);
                den += ex;
                acc.x += ac.x * ex; acc.y += ac.y * ex;
                acc.z += ac.z * ex; acc.w += ac.w * ex;
            }
        }
    }

    float inv = 1.f / den;
    int c = lane * 4;
    float o[4];
    o[0] = elu1(acc.x * inv + bias[c + 0]);
    o[1] = elu1(acc.y * inv + bias[c + 1]);
    o[2] = elu1(acc.z * inv + bias[c + 2]);
    o[3] = elu1(acc.w * inv + bias[c + 3]);
    __nv_bfloat16 h[4], l[4];
#pragma unroll
    for (int q = 0; q < 4; q++) split_bf(o[q], h[q], l[q]);
    size_t base = (size_t)w * 128;
    int p0 = permk(c), p1 = permk(c + 2);
    *(uint32_t*)(g_h1h + base + p0) = *(uint32_t*)&h[0];
    *(uint32_t*)(g_h1h + base + p1) = *(uint32_t*)&h[2];
    *(uint32_t*)(g_h1l + base + p0) = *(uint32_t*)&l[0];
    *(uint32_t*)(g_h1l + base + p1) = *(uint32_t*)&l[2];
}

// --------- layer 2 edge pass, CSR, warp per node, 4-deep gather prefetch ---------
__global__ void k_edge2_csr(const float* __restrict__ att,
                            const float* __restrict__ bias, int N) {
    int gt = blockIdx.x * blockDim.x + threadIdx.x;
    int lane = gt & 31, w = gt >> 5;
    if (w >= N) return;

    float2 attr = *(const float2*)(att + lane * 2);
    float2 b = *(const float2*)(g_xr2 + (size_t)w * 64 + lane * 2);

    int beg = g_rowptr[w];
    int n = g_rowptr[w + 1] - beg;
    float2 acc = make_float2(0.f, 0.f);
    float den = 0.f;

    float2 buf[4];
#pragma unroll
    for (int j = 0; j < 4; j++)
        if (j < n)
            buf[j] = *(const float2*)(g_xl2 + (size_t)g_esrc[beg + j] * 64 + lane * 2);

    for (int p0 = 0; p0 < n; p0 += 4) {
#pragma unroll
        for (int j = 0; j < 4; j++) {
            int p = p0 + j;
            if (p < n) {
                float2 ac = buf[j];
                if (p + 4 < n)
                    buf[j] = *(const float2*)(g_xl2 + (size_t)g_esrc[beg + p + 4] * 64 + lane * 2);
                float z0 = ac.x + b.x; z0 = z0 > 0.f ? z0 : 0.2f * z0;
                float z1 = ac.y + b.y; z1 = z1 > 0.f ? z1 : 0.2f * z1;
                float part = attr.x * z0 + attr.y * z1;
                part += __shfl_xor_sync(0xffffffffu, part, 1);
                part += __shfl_xor_sync(0xffffffffu, part, 2);
                part += __shfl_xor_sync(0xffffffffu, part, 4);
                part += __shfl_xor_sync(0xffffffffu, part, 8);
                part += __shfl_xor_sync(0xffffffffu, part, 16);
                float ex = __expf(part);
                den += ex;
                acc.x += ac.x * ex; acc.y += ac.y * ex;
            }
        }
    }

    float inv = 1.f / den;
    int c = lane * 2;
    float o0 = elu1(acc.x * inv + bias[c + 0]);
    float o1 = elu1(acc.y * inv + bias[c + 1]);
    __nv_bfloat16 h[2], l[2];
    split_bf(o0, h[0], l[0]);
    split_bf(o1, h[1], l[1]);
    size_t base = (size_t)w * 64;
    int p0 = permk(c);
    *(uint32_t*)(g_h2h + base + p0) = *(uint32_t*)&h[0];
    *(uint32_t*)(g_h2l + base + p0) = *(uint32_t*)&l[0];
}

// ------------------------- launch -------------------------
static inline int cdiv(int a, int b) { return (a + b - 1) / b; }

extern "C" void kernel_launch(void* const* d_in, const int* in_sizes, int n_in,
                              void* d_out, int out_size) {
    const float* x     = (const float*)d_in[0];
    const int*   ei    = (const int*)d_in[1];
    const float* Wl1   = (const float*)d_in[2];
    const float* bl1   = (const float*)d_in[3];
    const float* Wr1   = (const float*)d_in[4];
    const float* br1   = (const float*)d_in[5];
    const float* att1  = (const float*)d_in[6];
    const float* bias1 = (const float*)d_in[7];
    const float* Wl2   = (const float*)d_in[8];
    const float* bl2   = (const float*)d_in[9];
    const float* Wr2   = (const float*)d_in[10];
    const float* br2   = (const float*)d_in[11];
    const float* att2  = (const float*)d_in[12];
    const float* bias2 = (const float*)d_in[13];
    const float* Wlin  = (const float*)d_in[14];
    const float* blin  = (const float*)d_in[15];

    int N = in_sizes[0] / 128;
    int E = in_sizes[1] / 2;
    int Etot = E + N;
    int NB = cdiv(N, 256);
    int GW = 224;                              // weight-conversion blocks

    // ---- fork: CSR build on side stream, concurrent with cvt + GEMM1 ----
    cudaEventRecord(g_evFork, 0);
    cudaStreamWaitEvent(g_s2, g_evFork, 0);
    k_hist<<<cdiv(E, 256), 256, 0, g_s2>>>(ei, E);          // #1
    k_scanblk<<<NB, 256, 0, g_s2>>>(N);                     // #2

    // ---- main chain ----
    k_cvt<<<GW + cdiv(N * 128, 1024), 256>>>(x, N * 128, Wl1, Wr1, Wl2, Wr2, Wlin, GW);  // #3

    dim3 g1(cdiv(N, 128), 2);
    k_gemm_bf<128, 128, 0, 0, 1, 1><<<g1, 256>>>(bl1, br1, nullptr, N);   // #4 (profiled)

    k_finalize<<<NB, 256, 0, g_s2>>>(N, Etot, NB);          // #5 (side)
    k_scatter<<<cdiv(E, 256), 256, 0, g_s2>>>(ei, E);       // #6 (side)
    cudaEventRecord(g_evCsr, g_s2);

    // join: edge phase needs the CSR
    cudaStreamWaitEvent(0, g_evCsr, 0);
    k_edge1_csr<<<cdiv(N * 32, 256), 256>>>(att1, bias1, N);

    // layer 2
    dim3 g2(cdiv(N, 128), 2);
    k_gemm_bf<128, 64, 0, 1, 2, 2><<<g2, 256>>>(bl2, br2, nullptr, N);
    k_edge2_csr<<<cdiv(N * 32, 256), 256>>>(att2, bias2, N);

    // final linear + ELU -> d_out [N,128]
    dim3 g3(cdiv(N, 128), 1);
    k_gemm_bf<64, 128, 1, 2, 3, 0><<<g3, 256>>>(blin, blin, (float*)d_out, N);
}

// round 17
// speedup vs baseline: 1.1075x; 1.1075x over previous
#include <cuda_runtime.h>
#include <cuda_bf16.h>
#include <cstdint>

#define NMAX    50048
#define EMAX    800000
#define ETOTMAX (NMAX + EMAX)
#define NBLKMAX 256

// ------------------------- scratch (device globals) -------------------------
__device__ __align__(16) float g_xl1[NMAX * 128];
__device__ __align__(16) float g_xr1[NMAX * 128];
__device__ __align__(16) float g_xl2[NMAX * 64];
__device__ __align__(16) float g_xr2[NMAX * 64];
// bf16 hi/lo GEMM inputs, PERMUTED k-order within each row (see permk)
__device__ __align__(16) __nv_bfloat16 g_xh [NMAX * 128];
__device__ __align__(16) __nv_bfloat16 g_xlo[NMAX * 128];
__device__ __align__(16) __nv_bfloat16 g_h1h[NMAX * 128];
__device__ __align__(16) __nv_bfloat16 g_h1l[NMAX * 128];
__device__ __align__(16) __nv_bfloat16 g_h2h[NMAX * 64];
__device__ __align__(16) __nv_bfloat16 g_h2l[NMAX * 64];
// weights, transposed to [col][k] with permuted k, bf16 hi/lo
__device__ __align__(16) __nv_bfloat16 g_w1h[2 * 128 * 128];
__device__ __align__(16) __nv_bfloat16 g_w1l[2 * 128 * 128];
__device__ __align__(16) __nv_bfloat16 g_w2h[2 * 64 * 128];
__device__ __align__(16) __nv_bfloat16 g_w2l[2 * 64 * 128];
__device__ __align__(16) __nv_bfloat16 g_w3h[128 * 64];
__device__ __align__(16) __nv_bfloat16 g_w3l[128 * 64];
// CSR   (g_deg is ZERO at module load; k_finalize re-zeros it each run)
__device__ __align__(16) int g_deg[NMAX];
__device__ __align__(16) int g_pre[NMAX];
__device__ __align__(16) int g_bsum[NBLKMAX];
__device__ __align__(16) int g_rowptr[NMAX + 1];
__device__ __align__(16) int g_cursor[NMAX];
__device__ __align__(16) int g_esrc[ETOTMAX];

// ------------------------- helpers -------------------------
__device__ __forceinline__ float elu1(float v) { return v > 0.f ? v : expm1f(v); }

__device__ __forceinline__ void split_bf(float v, __nv_bfloat16& h, __nv_bfloat16& l) {
    h = __float2bfloat16_rn(v);
    l = __float2bfloat16_rn(v - __bfloat162float(h));
}

// permuted element index within a row: per 32-elem chunk, word j (2 elems) goes to
// slot pos(j) = (j%4)*4 + j/4, so a fragment thread's 4 words are one uint4.
__device__ __forceinline__ int permk(int k) {
    int chunk = k >> 5;
    int j = (k & 31) >> 1;
    int lo = k & 1;
    int pos = (j & 3) * 4 + (j >> 2);
    return chunk * 32 + pos * 2 + lo;
}

__device__ __forceinline__ void mma_bf16(float* c, const uint32_t* a, const uint32_t* b) {
    asm volatile(
        "mma.sync.aligned.m16n8k16.row.col.f32.bf16.bf16.f32 "
        "{%0,%1,%2,%3}, {%4,%5,%6,%7}, {%8,%9}, {%0,%1,%2,%3};\n"
        : "+f"(c[0]), "+f"(c[1]), "+f"(c[2]), "+f"(c[3])
        : "r"(a[0]), "r"(a[1]), "r"(a[2]), "r"(a[3]), "r"(b[0]), "r"(b[1]));
}

__device__ __forceinline__ uint32_t s2u(const void* p) {
    return (uint32_t)__cvta_generic_to_shared(p);
}
#define CP16(dst, src) \
    asm volatile("cp.async.cg.shared.global [%0], [%1], 16;\n" :: "r"(dst), "l"(src))
#define CP_COMMIT() asm volatile("cp.async.commit_group;\n" ::: "memory")
#define CP_WAIT0()  asm volatile("cp.async.wait_group 0;\n" ::: "memory")
#define CP_WAIT1()  asm volatile("cp.async.wait_group 1;\n" ::: "memory")

// ------------- side stream + events for CSR fork/join (created at load) -------------
static cudaStream_t g_s2;
static cudaEvent_t  g_evFork, g_evCsr;
namespace {
struct _StreamInit {
    _StreamInit() {
        cudaStreamCreateWithFlags(&g_s2, cudaStreamNonBlocking);
        cudaEventCreateWithFlags(&g_evFork, cudaEventDisableTiming);
        cudaEventCreateWithFlags(&g_evCsr, cudaEventDisableTiming);
    }
};
_StreamInit _streamInit;
}

// --------- merged conversion kernel: blocks [0, GW) do weights, rest do x ---------
__global__ void k_cvt(const float* __restrict__ x, int n,
                      const float* __restrict__ Wl1, const float* __restrict__ Wr1,
                      const float* __restrict__ Wl2, const float* __restrict__ Wr2,
                      const float* __restrict__ Wlin, int GW) {
    if ((int)blockIdx.x < GW) {
        int i = blockIdx.x * blockDim.x + threadIdx.x;   // 57344 total
        if (i < 32768) {                                  // L1: m, col(128), k(128)
            int m = i >> 14, r = i & 16383, c = r >> 7, k = r & 127;
            const float* W = m ? Wr1 : Wl1;
            int o = (m << 14) + (c << 7) + permk(k);
            split_bf(W[k * 128 + c], g_w1h[o], g_w1l[o]);
        } else if (i < 49152) {                           // L2: m, col(64), k(128)
            int j = i - 32768;
            int m = j >> 13, r = j & 8191, c = r >> 7, k = r & 127;
            const float* W = m ? Wr2 : Wl2;
            int o = (m << 13) + (c << 7) + permk(k);
            split_bf(W[k * 64 + c], g_w2h[o], g_w2l[o]);
        } else if (i < 57344) {                           // lin: col(128), k(64)
            int j = i - 49152;
            int c = j >> 6, k = j & 63;
            int o = (c << 6) + permk(k);
            split_bf(Wlin[k * 128 + c], g_w3h[o], g_w3l[o]);
        }
    } else {
        int i = ((blockIdx.x - GW) * blockDim.x + threadIdx.x) * 4;
        if (i < n) {
            float4 v = *(const float4*)(x + i);
            __nv_bfloat16 h[4], l[4];
            split_bf(v.x, h[0], l[0]); split_bf(v.y, h[1], l[1]);
            split_bf(v.z, h[2], l[2]); split_bf(v.w, h[3], l[3]);
            int base = i & ~127;
            int p0 = base + permk(i & 127);
            int p1 = base + permk((i & 127) + 2);
            *(uint32_t*)(g_xh  + p0) = *(uint32_t*)&h[0];
            *(uint32_t*)(g_xh  + p1) = *(uint32_t*)&h[2];
            *(uint32_t*)(g_xlo + p0) = *(uint32_t*)&l[0];
            *(uint32_t*)(g_xlo + p1) = *(uint32_t*)&l[2];
        }
    }
}

// ------------------------- CSR build -------------------------
__global__ void k_hist(const int* __restrict__ ei, int E) {
    int i = blockIdx.x * blockDim.x + threadIdx.x;
    if (i < E) atomicAdd(&g_deg[ei[E + i]], 1);
}
// block-level scan of (deg+1); deg itself stays un-reset until k_finalize
__global__ void k_scanblk(int N) {
    __shared__ int sh[256];
    int i = blockIdx.x * 256 + threadIdx.x;
    int v = (i < N) ? (g_deg[i] + 1) : 0;      // +1 = self-loop
    sh[threadIdx.x] = v;
    __syncthreads();
    for (int off = 1; off < 256; off <<= 1) {
        int t = (threadIdx.x >= off) ? sh[threadIdx.x - off] : 0;
        __syncthreads();
        sh[threadIdx.x] += t;
        __syncthreads();
    }
    if (i < N) g_pre[i] = sh[threadIdx.x] - v;   // exclusive
    if (threadIdx.x == 255) g_bsum[blockIdx.x] = sh[255];
}
// merged top-scan + finalize: every block redundantly scans g_bsum in smem
__global__ void k_finalize(int N, int Etot, int NB) {
    __shared__ int sh[256];
    __shared__ int exc[256];
    int t = threadIdx.x;
    int v = (t < NB) ? g_bsum[t] : 0;
    sh[t] = v;
    __syncthreads();
    for (int off = 1; off < 256; off <<= 1) {
        int u = (t >= off) ? sh[t - off] : 0;
        __syncthreads();
        sh[t] += u;
        __syncthreads();
    }
    exc[t] = sh[t] - v;
    __syncthreads();
    int i = blockIdx.x * 256 + t;
    if (i < N) {
        int rp = g_pre[i] + exc[i >> 8];
        g_rowptr[i] = rp;
        g_cursor[i] = rp + 1;
        g_esrc[rp] = i;                   // self-loop occupies first slot
        g_deg[i] = 0;                     // reset for next graph replay
        if (i == 0) g_rowptr[N] = Etot;
    }
}
__global__ void k_scatter(const int* __restrict__ ei, int E) {
    int i = blockIdx.x * blockDim.x + threadIdx.x;
    if (i < E) {
        int d = ei[E + i];
        int slot = atomicAdd(&g_cursor[d], 1);
        g_esrc[slot] = ei[i];
    }
}

// ----- bf16x3-split tensor GEMM, permuted-k inputs, 3-stage cp.async pipeline -----
// C[M,BN] = A[M,K] @ W[K,BN] + bias.  BM=128, BK=32, 256 thr = 8 warps (2m x 4n).
// ONE __syncthreads per chunk: fill targets buf c+2, compute reads buf c.
// SRC: 0 = g_xh/g_xlo (K=128), 1 = g_h1h/g_h1l (K=128), 2 = g_h2h/g_h2l (K=64).
// WSEL: 1 = g_w1 (+y*16384), 2 = g_w2 (+y*8192), 3 = g_w3.
// DSTSEL: 0 = Carg (ldc=BN), 1 = y-sel (xl1,xr1) ldc=128, 2 = y-sel (xl2,xr2) ldc=64.
template <int K, int BN, int ACT, int SRC, int WSEL, int DSTSEL>
__global__ __launch_bounds__(256, 2) void k_gemm_bf(const float* __restrict__ b0,
                                                    const float* __restrict__ b1,
                                                    float* __restrict__ Carg, int M) {
    const int NF = BN / 32;
    const int KU4 = K / 8;                    // uint4 per global row
    const int NC = K / 32;                    // k-chunks

    const __nv_bfloat16* Agh = (SRC == 0) ? g_xh : (SRC == 1 ? g_h1h : g_h2h);
    const __nv_bfloat16* Agl = (SRC == 0) ? g_xlo : (SRC == 1 ? g_h1l : g_h2l);
    const __nv_bfloat16* Bgh = (WSEL == 1) ? g_w1h + blockIdx.y * 16384
                              : (WSEL == 2) ? g_w2h + blockIdx.y * 8192 : g_w3h;
    const __nv_bfloat16* Bgl = (WSEL == 1) ? g_w1l + blockIdx.y * 16384
                              : (WSEL == 2) ? g_w2l + blockIdx.y * 8192 : g_w3l;
    const float* bias = (blockIdx.y == 0) ? b0 : b1;
    float* C;
    int ldc;
    if (DSTSEL == 0)      { C = Carg; ldc = BN; }
    else if (DSTSEL == 1) { C = (blockIdx.y == 0) ? g_xl1 : g_xr1; ldc = 128; }
    else                  { C = (blockIdx.y == 0) ? g_xl2 : g_xr2; ldc = 64; }

    // 3-stage buffers; rows of exactly 64B -> conflict-free LDS.128 frags
    __shared__ __nv_bfloat16 Ah[3][128][32];
    __shared__ __nv_bfloat16 Al[3][128][32];
    __shared__ __nv_bfloat16 Bh[3][BN][32];
    __shared__ __nv_bfloat16 Bl[3][BN][32];

    int tid  = threadIdx.x;
    int lane = tid & 31;
    int ww   = tid >> 5;
    int bm   = blockIdx.x * 128;
    int wm0  = (ww & 1) * 64;
    int wn0  = (ww >> 1) * (BN / 4);
    int tg   = lane & 3;
    int gid  = lane >> 2;

    // per-thread fill coordinates (chunk-invariant)
    int fa_row = tid >> 1, fa_q = (tid & 1) * 2;
    int fa_arow = bm + fa_row; if (fa_arow >= M) fa_arow = M - 1;
    const uint4* fa_ph = (const uint4*)Agh + (size_t)fa_arow * KU4;
    const uint4* fa_pl = (const uint4*)Agl + (size_t)fa_arow * KU4;

    float acc[4][NF][4] = {};

    auto fill = [&](int buf, int c) {
        int ck4 = c * 4;
        CP16(s2u(&Ah[buf][fa_row][fa_q * 8]),       fa_ph + ck4 + fa_q);
        CP16(s2u(&Ah[buf][fa_row][(fa_q + 1) * 8]), fa_ph + ck4 + fa_q + 1);
        CP16(s2u(&Al[buf][fa_row][fa_q * 8]),       fa_pl + ck4 + fa_q);
        CP16(s2u(&Al[buf][fa_row][(fa_q + 1) * 8]), fa_pl + ck4 + fa_q + 1);
#pragma unroll
        for (int q = tid; q < BN * 4; q += 256) {
            int col = q >> 2, part = q & 3;
            CP16(s2u(&Bh[buf][col][part * 8]),
                 (const uint4*)Bgh + (size_t)col * KU4 + ck4 + part);
            CP16(s2u(&Bl[buf][col][part * 8]),
                 (const uint4*)Bgl + (size_t)col * KU4 + ck4 + part);
        }
    };

    fill(0, 0);
    CP_COMMIT();
    if (NC > 1) { fill(1, 1); CP_COMMIT(); }

#pragma unroll
    for (int c = 0; c < NC; c++) {
        int buf = c % 3;
        if (c + 1 < NC) CP_WAIT1(); else CP_WAIT0();
        __syncthreads();                       // buf c ready; compute(c-1) done everywhere
        if (c + 2 < NC) { fill((c + 2) % 3, c + 2); CP_COMMIT(); }

        // B fragments for whole k-chunk (both k16 steps): 2*NF LDS.128
        uint4 vbh[NF], vbl[NF];
#pragma unroll
        for (int in = 0; in < NF; in++) {
            int nc = wn0 + in * 8 + gid;
            vbh[in] = *(const uint4*)&Bh[buf][nc][tg * 8];
            vbl[in] = *(const uint4*)&Bl[buf][nc][tg * 8];
        }

#pragma unroll
        for (int im = 0; im < 4; im++) {
            int mr = wm0 + im * 16 + gid;
            uint4 vh = *(const uint4*)&Ah[buf][mr][tg * 8];
            uint4 uh = *(const uint4*)&Ah[buf][mr + 8][tg * 8];
            uint4 vl = *(const uint4*)&Al[buf][mr][tg * 8];
            uint4 ul = *(const uint4*)&Al[buf][mr + 8][tg * 8];
            uint32_t ah0[4] = {vh.x, uh.x, vh.y, uh.y};   // s = 0
            uint32_t ah1[4] = {vh.z, uh.z, vh.w, uh.w};   // s = 1
            uint32_t al0[4] = {vl.x, ul.x, vl.y, ul.y};
            uint32_t al1[4] = {vl.z, ul.z, vl.w, ul.w};
#pragma unroll
            for (int in = 0; in < NF; in++) {
                uint32_t bh0[2] = {vbh[in].x, vbh[in].y};
                uint32_t bh1[2] = {vbh[in].z, vbh[in].w};
                uint32_t bl0[2] = {vbl[in].x, vbl[in].y};
                uint32_t bl1[2] = {vbl[in].z, vbl[in].w};
                mma_bf16(acc[im][in], ah0, bh0);
                mma_bf16(acc[im][in], ah0, bl0);
                mma_bf16(acc[im][in], al0, bh0);
                mma_bf16(acc[im][in], ah1, bh1);
                mma_bf16(acc[im][in], ah1, bl1);
                mma_bf16(acc[im][in], al1, bh1);
            }
        }
    }

#pragma unroll
    for (int im = 0; im < 4; im++) {
        int r0 = bm + wm0 + im * 16 + gid;
#pragma unroll
        for (int in = 0; in < NF; in++) {
            int cc = wn0 + in * 8 + 2 * tg;
            float bx = bias[cc], by = bias[cc + 1];
            if (r0 < M) {
                float2 v = make_float2(acc[im][in][0] + bx, acc[im][in][1] + by);
                if (ACT) { v.x = elu1(v.x); v.y = elu1(v.y); }
                *(float2*)(C + (size_t)r0 * ldc + cc) = v;
            }
            if (r0 + 8 < M) {
                float2 v = make_float2(acc[im][in][2] + bx, acc[im][in][3] + by);
                if (ACT) { v.x = elu1(v.x); v.y = elu1(v.y); }
                *(float2*)(C + (size_t)(r0 + 8) * ldc + cc) = v;
            }
        }
    }
}

// --------- layer 1 edge phase, CSR, warp per node; writes h1 as permuted bf16 hi/lo ---------
__global__ void k_edge1_csr(const float* __restrict__ att,
                            const float* __restrict__ bias, int N) {
    int gt = blockIdx.x * blockDim.x + threadIdx.x;
    int lane = gt & 31, w = gt >> 5;
    if (w >= N) return;

    float4 attr = *(const float4*)(att + lane * 4);
    float4 b = *(const float4*)(g_xr1 + (size_t)w * 128 + lane * 4);

    int beg = g_rowptr[w], end = g_rowptr[w + 1];
    float4 acc = make_float4(0.f, 0.f, 0.f, 0.f);
    float den = 0.f;

    int s = g_esrc[beg];
    float4 a = *(const float4*)(g_xl1 + (size_t)s * 128 + lane * 4);
    for (int p = beg; p < end; p++) {
        float4 ac = a;
        if (p + 1 < end) {
            s = g_esrc[p + 1];
            a = *(const float4*)(g_xl1 + (size_t)s * 128 + lane * 4);
        }
        float z0 = ac.x + b.x; z0 = z0 > 0.f ? z0 : 0.2f * z0;
        float z1 = ac.y + b.y; z1 = z1 > 0.f ? z1 : 0.2f * z1;
        float z2 = ac.z + b.z; z2 = z2 > 0.f ? z2 : 0.2f * z2;
        float z3 = ac.w + b.w; z3 = z3 > 0.f ? z3 : 0.2f * z3;
        float part = attr.x * z0 + attr.y * z1 + attr.z * z2 + attr.w * z3;
        part += __shfl_xor_sync(0xffffffffu, part, 1);
        part += __shfl_xor_sync(0xffffffffu, part, 2);
        float ex = __expf(part);
        den += ex;
        acc.x += ac.x * ex; acc.y += ac.y * ex;
        acc.z += ac.z * ex; acc.w += ac.w * ex;
    }

    float inv = 1.f / den;
    int c = lane * 4;
    float o[4];
    o[0] = elu1(acc.x * inv + bias[c + 0]);
    o[1] = elu1(acc.y * inv + bias[c + 1]);
    o[2] = elu1(acc.z * inv + bias[c + 2]);
    o[3] = elu1(acc.w * inv + bias[c + 3]);
    __nv_bfloat16 h[4], l[4];
#pragma unroll
    for (int q = 0; q < 4; q++) split_bf(o[q], h[q], l[q]);
    size_t base = (size_t)w * 128;
    int p0 = permk(c), p1 = permk(c + 2);
    *(uint32_t*)(g_h1h + base + p0) = *(uint32_t*)&h[0];
    *(uint32_t*)(g_h1h + base + p1) = *(uint32_t*)&h[2];
    *(uint32_t*)(g_h1l + base + p0) = *(uint32_t*)&l[0];
    *(uint32_t*)(g_h1l + base + p1) = *(uint32_t*)&l[2];
}

// --------- layer 2 edge pass, CSR, warp per node; writes h2 as permuted bf16 hi/lo ---------
__global__ void k_edge2_csr(const float* __restrict__ att,
                            const float* __restrict__ bias, int N) {
    int gt = blockIdx.x * blockDim.x + threadIdx.x;
    int lane = gt & 31, w = gt >> 5;
    if (w >= N) return;

    float2 attr = *(const float2*)(att + lane * 2);
    float2 b = *(const float2*)(g_xr2 + (size_t)w * 64 + lane * 2);

    int beg = g_rowptr[w], end = g_rowptr[w + 1];
    float2 acc = make_float2(0.f, 0.f);
    float den = 0.f;

    int s = g_esrc[beg];
    float2 a = *(const float2*)(g_xl2 + (size_t)s * 64 + lane * 2);
    for (int p = beg; p < end; p++) {
        float2 ac = a;
        if (p + 1 < end) {
            s = g_esrc[p + 1];
            a = *(const float2*)(g_xl2 + (size_t)s * 64 + lane * 2);
        }
        float z0 = ac.x + b.x; z0 = z0 > 0.f ? z0 : 0.2f * z0;
        float z1 = ac.y + b.y; z1 = z1 > 0.f ? z1 : 0.2f * z1;
        float part = attr.x * z0 + attr.y * z1;
        part += __shfl_xor_sync(0xffffffffu, part, 1);
        part += __shfl_xor_sync(0xffffffffu, part, 2);
        part += __shfl_xor_sync(0xffffffffu, part, 4);
        part += __shfl_xor_sync(0xffffffffu, part, 8);
        part += __shfl_xor_sync(0xffffffffu, part, 16);
        float ex = __expf(part);
        den += ex;
        acc.x += ac.x * ex; acc.y += ac.y * ex;
    }

    float inv = 1.f / den;
    int c = lane * 2;
    float o0 = elu1(acc.x * inv + bias[c + 0]);
    float o1 = elu1(acc.y * inv + bias[c + 1]);
    __nv_bfloat16 h[2], l[2];
    split_bf(o0, h[0], l[0]);
    split_bf(o1, h[1], l[1]);
    size_t base = (size_t)w * 64;
    int p0 = permk(c);
    *(uint32_t*)(g_h2h + base + p0) = *(uint32_t*)&h[0];
    *(uint32_t*)(g_h2l + base + p0) = *(uint32_t*)&l[0];
}

// ------------------------- launch -------------------------
static inline int cdiv(int a, int b) { return (a + b - 1) / b; }

extern "C" void kernel_launch(void* const* d_in, const int* in_sizes, int n_in,
                              void* d_out, int out_size) {
    const float* x     = (const float*)d_in[0];
    const int*   ei    = (const int*)d_in[1];
    const float* Wl1   = (const float*)d_in[2];
    const float* bl1   = (const float*)d_in[3];
    const float* Wr1   = (const float*)d_in[4];
    const float* br1   = (const float*)d_in[5];
    const float* att1  = (const float*)d_in[6];
    const float* bias1 = (const float*)d_in[7];
    const float* Wl2   = (const float*)d_in[8];
    const float* bl2   = (const float*)d_in[9];
    const float* Wr2   = (const float*)d_in[10];
    const float* br2   = (const float*)d_in[11];
    const float* att2  = (const float*)d_in[12];
    const float* bias2 = (const float*)d_in[13];
    const float* Wlin  = (const float*)d_in[14];
    const float* blin  = (const float*)d_in[15];

    int N = in_sizes[0] / 128;
    int E = in_sizes[1] / 2;
    int Etot = E + N;
    int NB = cdiv(N, 256);
    int GW = 224;                              // weight-conversion blocks

    // ---- fork: CSR build on side stream, concurrent with cvt + GEMM1 ----
    cudaEventRecord(g_evFork, 0);
    cudaStreamWaitEvent(g_s2, g_evFork, 0);
    k_hist<<<cdiv(E, 256), 256, 0, g_s2>>>(ei, E);
    k_scanblk<<<NB, 256, 0, g_s2>>>(N);

    // ---- main chain ----
    k_cvt<<<GW + cdiv(N * 128, 1024), 256>>>(x, N * 128, Wl1, Wr1, Wl2, Wr2, Wlin, GW);

    dim3 g1(cdiv(N, 128), 2);
    k_gemm_bf<128, 128, 0, 0, 1, 1><<<g1, 256>>>(bl1, br1, nullptr, N);

    k_finalize<<<NB, 256, 0, g_s2>>>(N, Etot, NB);
    k_scatter<<<cdiv(E, 256), 256, 0, g_s2>>>(ei, E);
    cudaEventRecord(g_evCsr, g_s2);

    // join: edge phase needs the CSR
    cudaStreamWaitEvent(0, g_evCsr, 0);
    k_edge1_csr<<<cdiv(N * 32, 256), 256>>>(att1, bias1, N);

    // layer 2
    dim3 g2(cdiv(N, 128), 2);
    k_gemm_bf<128, 64, 0, 1, 2, 2><<<g2, 256>>>(bl2, br2, nullptr, N);
    k_edge2_csr<<<cdiv(N * 32, 256), 256>>>(att2, bias2, N);

    // final linear + ELU -> d_out [N,128]
    dim3 g3(cdiv(N, 128), 1);
    k_gemm_bf<64, 128, 1, 2, 3, 0><<<g3, 256>>>(blin, blin, (float*)d_out, N);
}